// round 15
// baseline (speedup 1.0000x reference)
#include <cuda_runtime.h>
#include <cuda_fp16.h>
#include <cstdint>

#define D 512
#define BN 1024          // B*N = 8*128
#define NPAIR 128        // m per (b,n)
#define L2DIM 256        // W2 output width
#define KC 32            // K per chunk
#define CHUNKS 16        // 512/32
#define HROWB 80         // smem row stride bytes (conflict-free ldmatrix)
#define WROWB 80

// dyn smem layout for k2 (bytes) — l-split version (128 l per block)
#define OFF_AROW 0                   // 512*4 = 2048
#define OFF_B2   2048                // 128*4 = 512
#define OFF_W3   2560                // 128*4*4 = 2048
#define OFF_PART 4608                // 128*8*4 = 4096
#define OFF_H    8704                // 2 * 128*80 = 20480
#define OFF_W    29184               // 2 * 128*80 = 20480
#define SMEM_K2  49664

typedef unsigned long long ull;

// Scratch (allocation-free rule: __device__ globals)
__device__ float  g_A[BN * D];        // h1 + pc + b1   (indexed by n-row)
__device__ float  g_B[BN * D];        // h2 - pc        (indexed by m-row)
__device__ __half g_W2h[L2DIM * D];   // W2 transposed [l][k], fp16
__device__ __half g_fh[BN * D];       // f in fp16
__device__ __half g_W1h[1024 * D];    // [W1a|W1b] transposed [j][d], fp16

// ---------------- helpers ----------------
__device__ __forceinline__ uint32_t smem_u32(const void* p) {
    uint32_t a;
    asm("{ .reg .u64 t; cvta.to.shared.u64 t, %1; cvt.u32.u64 %0, t; }" : "=r"(a) : "l"(p));
    return a;
}
__device__ __forceinline__ void cp_async16(uint32_t dst, const void* src) {
    asm volatile("cp.async.cg.shared.global [%0], [%1], 16;" :: "r"(dst), "l"(src) : "memory");
}
#define CP_COMMIT() asm volatile("cp.async.commit_group;" ::: "memory")
#define CP_WAIT0()  asm volatile("cp.async.wait_group 0;" ::: "memory")

__device__ __forceinline__ void ldsm4(uint32_t* r, uint32_t addr) {
    asm volatile("ldmatrix.sync.aligned.m8n8.x4.shared.b16 {%0,%1,%2,%3}, [%4];"
        : "=r"(r[0]), "=r"(r[1]), "=r"(r[2]), "=r"(r[3]) : "r"(addr));
}
__device__ __forceinline__ void mma_f16(float* d, const uint32_t* a, const uint32_t* b) {
    asm volatile(
        "mma.sync.aligned.m16n8k16.row.col.f32.f16.f16.f32 "
        "{%0,%1,%2,%3}, {%4,%5,%6,%7}, {%8,%9}, {%0,%1,%2,%3};"
        : "+f"(d[0]), "+f"(d[1]), "+f"(d[2]), "+f"(d[3])
        : "r"(a[0]), "r"(a[1]), "r"(a[2]), "r"(a[3]), "r"(b[0]), "r"(b[1]));
}
__device__ __forceinline__ uint32_t packh2(float x, float y) {
    __half2 h = __floats2half2_rn(x, y);
    return *reinterpret_cast<uint32_t*>(&h);
}

// ================= Kernel 0: data prep =================
// y <  16 : transpose+convert W1[0:1024] -> g_W1h[j][d]   (64x64 tiles)
// y 16-17 : convert f -> g_fh
// y 18-21 : transpose+convert W2 -> g_W2h[l][k]
// y 22-23 : zero the output buffer (atomicAdd epilogue target)
__global__ __launch_bounds__(256) void k0_prep(
    const float* __restrict__ f, const float* __restrict__ W1,
    const float* __restrict__ W2, float* __restrict__ out)
{
    const int t = threadIdx.x;
    if (blockIdx.y < 16) {
        __shared__ float tile[64][65];
        const int d0  = blockIdx.x * 64;
        const int jg0 = blockIdx.y * 64;
        const int rbase = (jg0 >= 512 ? 512 : 0) + d0;
        const int cbase = jg0 & 511;
        #pragma unroll
        for (int i = 0; i < 16; i++) {
            int idx = i * 256 + t;
            int r = idx >> 6, cc = idx & 63;
            tile[r][cc] = W1[(rbase + r) * D + cbase + cc];
        }
        __syncthreads();
        #pragma unroll
        for (int j = 0; j < 2; j++) {
            int row = j * 32 + (t >> 3);
            int ch  = t & 7;
            uint32_t hp[4];
            #pragma unroll
            for (int q = 0; q < 4; q++)
                hp[q] = packh2(tile[ch * 8 + 2 * q][row], tile[ch * 8 + 2 * q + 1][row]);
            *reinterpret_cast<uint4*>(&g_W1h[(jg0 + row) * D + d0 + ch * 8]) =
                make_uint4(hp[0], hp[1], hp[2], hp[3]);
        }
        return;
    }
    if (blockIdx.y < 18) {
        int gid = ((blockIdx.y - 16) * 8 + blockIdx.x) * 256 + t;
        #pragma unroll
        for (int i = 0; i < 32; i++) {
            int p4 = gid + i * 4096;
            float4 v = *reinterpret_cast<const float4*>(&f[p4 * 4]);
            uint2 o;
            o.x = packh2(v.x, v.y);
            o.y = packh2(v.z, v.w);
            *reinterpret_cast<uint2*>(&g_fh[p4 * 4]) = o;
        }
        return;
    }
    if (blockIdx.y < 22) {
        __shared__ float tile[64][65];
        const int k0 = blockIdx.x * 64;
        const int l0 = (blockIdx.y - 18) * 64;
        #pragma unroll
        for (int i = 0; i < 16; i++) {
            int idx = i * 256 + t;
            int r = idx >> 6, cc = idx & 63;
            tile[r][cc] = W2[(k0 + r) * L2DIM + l0 + cc];
        }
        __syncthreads();
        #pragma unroll
        for (int j = 0; j < 2; j++) {
            int row = j * 32 + (t >> 3);
            int ch  = t & 7;
            uint32_t hp[4];
            #pragma unroll
            for (int q = 0; q < 4; q++)
                hp[q] = packh2(tile[ch * 8 + 2 * q][row], tile[ch * 8 + 2 * q + 1][row]);
            *reinterpret_cast<uint4*>(&g_W2h[(l0 + row) * D + k0 + ch * 8]) =
                make_uint4(hp[0], hp[1], hp[2], hp[3]);
        }
        return;
    }
    {
        // zero out: 16 blocks, each a contiguous 32768-float span
        // (256 thr x 4 floats = 1024 floats per i-step, 32 steps)
        int blk = (blockIdx.y - 22) * 8 + blockIdx.x;    // 0..15
        float4 z = make_float4(0.f, 0.f, 0.f, 0.f);
        #pragma unroll
        for (int i = 0; i < 32; i++)
            *reinterpret_cast<float4*>(&out[(size_t)blk * 32768 + i * 1024 + t * 4]) = z;
    }
}

// ================= Kernel 1: fp16 mma GEMM  C = f @ [W1a|W1b]^T =================
#define K1_FOFF 0
#define K1_WOFF 10240
#define K1_PC0  30720
#define K1_PC1  31232
#define K1_B1   31744
__global__ __launch_bounds__(256, 1) void k1_mma(
    const float* __restrict__ pos, const float* __restrict__ W1,
    const float* __restrict__ b1)
{
    __shared__ __align__(16) char sm[32256];
    const uint32_t sb = smem_u32(sm);
    float* pc0s = (float*)(sm + K1_PC0);
    float* pc1s = (float*)(sm + K1_PC1);
    float* b1s  = (float*)(sm + K1_B1);

    const int t = threadIdx.x, wid = t >> 5, lane = t & 31;
    const int wm = wid >> 2, wl = wid & 3;
    const int m0 = wm * 32, l0 = wl * 32;
    const int j0   = blockIdx.x * 128;
    const int row0 = blockIdx.y * 64;
    const int jc   = j0 & 511;
    const bool isA = (j0 < 512);

    if (t < 128) {
        pc0s[t] = W1[(2 * D) * D + jc + t];
        pc1s[t] = W1[(2 * D + 1) * D + jc + t];
        b1s[t]  = b1[jc + t];
    }

    const int frow = t >> 2, fch = t & 3;
    const int wrow = t >> 1, wch = (t & 1) * 2;

    float acc[2][4][4];
    #pragma unroll
    for (int mt = 0; mt < 2; mt++)
        #pragma unroll
        for (int nt = 0; nt < 4; nt++)
            #pragma unroll
            for (int c = 0; c < 4; c++) acc[mt][nt][c] = 0.f;

    cp_async16(sb + K1_FOFF + frow * HROWB + fch * 16, &g_fh[(row0 + frow) * D + fch * 8]);
    cp_async16(sb + K1_WOFF + wrow * WROWB + wch * 16,       &g_W1h[(j0 + wrow) * D + wch * 8]);
    cp_async16(sb + K1_WOFF + wrow * WROWB + (wch + 1) * 16, &g_W1h[(j0 + wrow) * D + (wch + 1) * 8]);
    CP_COMMIT();
    CP_WAIT0();
    __syncthreads();

    const int fr = lane & 15, fc = lane >> 4;

    for (int c = 0; c < CHUNKS; c++) {
        const int buf = c & 1;
        const bool more = (c + 1 < CHUNKS);

        if (more) {
            const int kn = (c + 1) * KC;
            cp_async16(sb + K1_FOFF + (buf ^ 1) * 64 * HROWB + frow * HROWB + fch * 16,
                       &g_fh[(row0 + frow) * D + kn + fch * 8]);
            cp_async16(sb + K1_WOFF + (buf ^ 1) * 128 * WROWB + wrow * WROWB + wch * 16,
                       &g_W1h[(j0 + wrow) * D + kn + wch * 8]);
            cp_async16(sb + K1_WOFF + (buf ^ 1) * 128 * WROWB + wrow * WROWB + (wch + 1) * 16,
                       &g_W1h[(j0 + wrow) * D + kn + (wch + 1) * 8]);
            CP_COMMIT();
        }

        const uint32_t Fb = sb + K1_FOFF + buf * 64 * HROWB;
        const uint32_t Wb = sb + K1_WOFF + buf * 128 * WROWB;
        #pragma unroll
        for (int ks = 0; ks < 2; ks++) {
            const int kb = ks * 32 + fc * 16;
            uint32_t af[2][4];
            #pragma unroll
            for (int mt = 0; mt < 2; mt++)
                ldsm4(af[mt], Fb + (m0 + mt * 16 + fr) * HROWB + kb);
            uint32_t bf[2][4];
            #pragma unroll
            for (int g = 0; g < 2; g++)
                ldsm4(bf[g], Wb + (l0 + g * 16 + fr) * WROWB + kb);
            #pragma unroll
            for (int mt = 0; mt < 2; mt++)
                #pragma unroll
                for (int g = 0; g < 2; g++) {
                    uint32_t blo[2] = {bf[g][0], bf[g][2]};
                    uint32_t bhi[2] = {bf[g][1], bf[g][3]};
                    mma_f16(acc[mt][2 * g],     af[mt], blo);
                    mma_f16(acc[mt][2 * g + 1], af[mt], bhi);
                }
        }
        CP_WAIT0();
        __syncthreads();
    }

    const int lr = lane >> 2, lc = lane & 3;
    #pragma unroll
    for (int mt = 0; mt < 2; mt++) {
        #pragma unroll
        for (int half = 0; half < 2; half++) {
            int row = row0 + m0 + mt * 16 + lr + half * 8;
            float p0 = pos[row * 2 + 0];
            float p1 = pos[row * 2 + 1];
            #pragma unroll
            for (int nt = 0; nt < 4; nt++) {
                int jl = l0 + nt * 8 + 2 * lc;
                float c0 = acc[mt][nt][half * 2 + 0];
                float c1 = acc[mt][nt][half * 2 + 1];
                float pcv0 = p0 * pc0s[jl]     + p1 * pc1s[jl];
                float pcv1 = p0 * pc0s[jl + 1] + p1 * pc1s[jl + 1];
                float2 o;
                if (isA) {
                    o.x = c0 + pcv0 + b1s[jl];
                    o.y = c1 + pcv1 + b1s[jl + 1];
                    *reinterpret_cast<float2*>(&g_A[row * D + jc + jl]) = o;
                } else {
                    o.x = c0 - pcv0;
                    o.y = c1 - pcv1;
                    *reinterpret_cast<float2*>(&g_B[row * D + jc + jl]) = o;
                }
            }
        }
    }
}

// ================= Kernel 2: fp16 mma GEMM, 2 blocks per bn (l-split) =========
// 2048 blocks = (bn, lhalf). 256 thr = 8 warps (4m x 2l), warp tile 32x64.
// Each block owns 128 of 256 W2 columns: W2 traffic UNchanged vs single-block,
// H staging duplicated (Bt LDG x2). 2 blocks/SM -> 2 independent sync domains.
// Epilogue: partial l-reduction + atomicAdd into zeroed out (b3 by lhalf 0).
__global__ __launch_bounds__(256, 2) void k2_mma(
    const float* __restrict__ b2, const float* __restrict__ W3,
    const float* __restrict__ b3, float* __restrict__ out)
{
    extern __shared__ char smem[];
    const uint32_t sb = smem_u32(smem);
    float* aR   = (float*)(smem + OFF_AROW);
    float* b2s  = (float*)(smem + OFF_B2);
    float* w3s  = (float*)(smem + OFF_W3);
    float* part = (float*)(smem + OFF_PART);

    const int t = threadIdx.x, wid = t >> 5, lane = t & 31;
    const int wm = wid >> 1, wl = wid & 1;
    const int m0 = wm * 32, l0 = wl * 64;          // l0 local within 128
    const int bn = blockIdx.x >> 1;
    const int lh = blockIdx.x & 1;
    const int b  = bn >> 7;
    const float* Btb = g_B + (size_t)b * NPAIR * D;
    const __half* W2base = g_W2h + (size_t)(lh * 128) * D;

    // staging roles
    const int hrow = t >> 1;            // H row (2 thr/row, 128 rows)
    const int hko  = (t & 1) * 16;      // 16-float half of 32k
    const int wrow = t >> 1;            // W row (2 thr/row, 128 rows)
    const int wch  = (t & 1) * 2;       // 2 x 16B chunks

    aR[t] = g_A[bn * D + t];
    aR[t + 256] = g_A[bn * D + 256 + t];
    if (t < 128) {
        b2s[t] = b2[lh * 128 + t];
        #pragma unroll
        for (int o = 0; o < 4; o++) w3s[t * 4 + o] = W3[(lh * 128 + t) * 4 + o];
    }
    __syncthreads();

    float acc[2][8][4];
    #pragma unroll
    for (int mt = 0; mt < 2; mt++)
        #pragma unroll
        for (int nt = 0; nt < 8; nt++)
            #pragma unroll
            for (int c = 0; c < 4; c++) acc[mt][nt][c] = 0.f;

    // ---- chunk 0 ----
    {
        uint32_t wdst = sb + OFF_W + wrow * WROWB + wch * 16;
        cp_async16(wdst,      &W2base[wrow * D + wch * 8]);
        cp_async16(wdst + 16, &W2base[wrow * D + wch * 8 + 8]);
        CP_COMMIT();

        const float* bp = &Btb[hrow * D + hko];
        const float* ar = aR + hko;
        uint32_t hp[8];
        #pragma unroll
        for (int q = 0; q < 4; q++) {
            float4 v = *reinterpret_cast<const float4*>(bp + q * 4);
            hp[2*q]   = packh2(fmaxf(v.x + ar[q*4+0], 0.f), fmaxf(v.y + ar[q*4+1], 0.f));
            hp[2*q+1] = packh2(fmaxf(v.z + ar[q*4+2], 0.f), fmaxf(v.w + ar[q*4+3], 0.f));
        }
        char* hdst = (char*)smem + OFF_H + hrow * HROWB + (t & 1) * 32;
        *reinterpret_cast<uint4*>(hdst)      = make_uint4(hp[0], hp[1], hp[2], hp[3]);
        *reinterpret_cast<uint4*>(hdst + 16) = make_uint4(hp[4], hp[5], hp[6], hp[7]);
        CP_WAIT0();
        __syncthreads();
    }

    const int fr = lane & 15;
    const int fc = lane >> 4;

    for (int c = 0; c < CHUNKS; c++) {
        const int buf = c & 1;
        const bool more = (c + 1 < CHUNKS);
        float4 rB[4];

        if (more) {
            const int kn = (c + 1) * KC;
            uint32_t wdst = sb + OFF_W + (buf ^ 1) * 128 * WROWB + wrow * WROWB + wch * 16;
            cp_async16(wdst,      &W2base[wrow * D + kn + wch * 8]);
            cp_async16(wdst + 16, &W2base[wrow * D + kn + wch * 8 + 8]);
            CP_COMMIT();
            const float* bp = &Btb[hrow * D + kn + hko];
            #pragma unroll
            for (int q = 0; q < 4; q++)
                rB[q] = *reinterpret_cast<const float4*>(bp + q * 4);
        }

        // ---- compute chunk c ----
        const uint32_t Hb = sb + OFF_H + buf * 128 * HROWB;
        const uint32_t Wb = sb + OFF_W + buf * 128 * WROWB;
        #pragma unroll
        for (int ks = 0; ks < 2; ks++) {
            const int kb = ks * 32 + fc * 16;
            uint32_t af[2][4];
            #pragma unroll
            for (int mt = 0; mt < 2; mt++)
                ldsm4(af[mt], Hb + (m0 + mt * 16 + fr) * HROWB + kb);
            uint32_t bf[4][4];
            #pragma unroll
            for (int g = 0; g < 4; g++)
                ldsm4(bf[g], Wb + (l0 + g * 16 + fr) * WROWB + kb);
            #pragma unroll
            for (int mt = 0; mt < 2; mt++)
                #pragma unroll
                for (int g = 0; g < 4; g++) {
                    uint32_t blo[2] = {bf[g][0], bf[g][2]};
                    uint32_t bhi[2] = {bf[g][1], bf[g][3]};
                    mma_f16(acc[mt][2 * g],     af[mt], blo);
                    mma_f16(acc[mt][2 * g + 1], af[mt], bhi);
                }
        }

        if (more) {
            const float* ar = aR + (c + 1) * KC + hko;
            uint32_t hp[8];
            #pragma unroll
            for (int q = 0; q < 4; q++) {
                hp[2*q]   = packh2(fmaxf(rB[q].x + ar[q*4+0], 0.f), fmaxf(rB[q].y + ar[q*4+1], 0.f));
                hp[2*q+1] = packh2(fmaxf(rB[q].z + ar[q*4+2], 0.f), fmaxf(rB[q].w + ar[q*4+3], 0.f));
            }
            char* hdst = (char*)smem + OFF_H + (buf ^ 1) * 128 * HROWB + hrow * HROWB + (t & 1) * 32;
            *reinterpret_cast<uint4*>(hdst)      = make_uint4(hp[0], hp[1], hp[2], hp[3]);
            *reinterpret_cast<uint4*>(hdst + 16) = make_uint4(hp[4], hp[5], hp[6], hp[7]);
        }
        CP_WAIT0();
        __syncthreads();
    }

    // ---- epilogue: relu(acc + b2) @ W3 (local l-half), reduce over 2 l-warps ----
    const int lr = lane >> 2, lc = lane & 3;
    #pragma unroll
    for (int mt = 0; mt < 2; mt++) {
        float o0[4] = {0.f, 0.f, 0.f, 0.f};
        float o1[4] = {0.f, 0.f, 0.f, 0.f};
        #pragma unroll
        for (int nt = 0; nt < 8; nt++) {
            int lcol = l0 + 8 * nt + 2 * lc;
            float vb0 = b2s[lcol], vb1 = b2s[lcol + 1];
            const float* w30 = &w3s[lcol * 4];
            const float* w31 = &w3s[(lcol + 1) * 4];
            float v00 = fmaxf(acc[mt][nt][0] + vb0, 0.f);
            float v01 = fmaxf(acc[mt][nt][1] + vb1, 0.f);
            float v10 = fmaxf(acc[mt][nt][2] + vb0, 0.f);
            float v11 = fmaxf(acc[mt][nt][3] + vb1, 0.f);
            #pragma unroll
            for (int o = 0; o < 4; o++) {
                o0[o] += v00 * w30[o] + v01 * w31[o];
                o1[o] += v10 * w30[o] + v11 * w31[o];
            }
        }
        #pragma unroll
        for (int off = 1; off <= 2; off <<= 1) {
            #pragma unroll
            for (int o = 0; o < 4; o++) {
                o0[o] += __shfl_xor_sync(0xffffffffu, o0[o], off);
                o1[o] += __shfl_xor_sync(0xffffffffu, o1[o], off);
            }
        }
        if (lc == 0) {
            int r0 = m0 + 16 * mt + lr;
            #pragma unroll
            for (int o = 0; o < 4; o++) {
                part[r0 * 8 + wl * 4 + o] = o0[o];
                part[(r0 + 8) * 8 + wl * 4 + o] = o1[o];
            }
        }
    }
    __syncthreads();

    if (t < 128) {
        #pragma unroll
        for (int o = 0; o < 4; o++) {
            float s = part[t * 8 + o] + part[t * 8 + 4 + o];
            if (lh == 0) s += b3[o];
            atomicAdd(&out[((size_t)bn * NPAIR + t) * 4 + o], s);
        }
    }
}

extern "C" void kernel_launch(void* const* d_in, const int* in_sizes, int n_in,
                              void* d_out, int out_size)
{
    const float* f   = (const float*)d_in[0];
    const float* pos = (const float*)d_in[1];
    const float* W1  = (const float*)d_in[2];
    const float* b1  = (const float*)d_in[3];
    const float* W2  = (const float*)d_in[4];
    const float* b2  = (const float*)d_in[5];
    const float* W3  = (const float*)d_in[6];
    const float* b3  = (const float*)d_in[7];
    float* out = (float*)d_out;

    cudaFuncSetAttribute(k2_mma, cudaFuncAttributeMaxDynamicSharedMemorySize, SMEM_K2);

    k0_prep<<<dim3(8, 24), 256>>>(f, W1, W2, out);
    k1_mma<<<dim3(8, 16), 256>>>(pos, W1, b1);
    k2_mma<<<2048, 256, SMEM_K2>>>(b2, W3, b3, out);
}

// round 16
// speedup vs baseline: 1.2618x; 1.2618x over previous
#include <cuda_runtime.h>
#include <cuda_fp16.h>
#include <cstdint>

#define D 512
#define BN 1024          // B*N = 8*128
#define NPAIR 128        // m per (b,n)
#define L2DIM 256        // W2 output width
#define KC 32            // K per chunk
#define CHUNKS 16        // 512/32
#define HROWB 80         // smem row stride bytes (conflict-free ldmatrix)
#define WROWB 80

// dyn smem layout for k2 (bytes)
#define OFF_AROW 0                   // 512*4 = 2048
#define OFF_B2   2048                // 1024
#define OFF_W3   3072                // 4096
#define OFF_PART 7168                // 128*16*4 = 8192
#define OFF_H    15360               // 2 * 128*80 = 20480
#define OFF_W    35840               // 2 * 256*80 = 40960
#define SMEM_TOTAL 76800

typedef unsigned long long ull;

// Scratch (allocation-free rule: __device__ globals)
__device__ float  g_A[BN * D];        // h1 + pc + b1   (indexed by n-row)
__device__ float  g_B[BN * D];        // h2 - pc        (indexed by m-row)
__device__ __half g_W2h[L2DIM * D];   // W2 transposed [l][k], fp16
__device__ __half g_fh[BN * D];       // f in fp16
__device__ __half g_W1h[1024 * D];    // [W1a|W1b] transposed [j][d], fp16

// ---------------- helpers ----------------
__device__ __forceinline__ uint32_t smem_u32(const void* p) {
    uint32_t a;
    asm("{ .reg .u64 t; cvta.to.shared.u64 t, %1; cvt.u32.u64 %0, t; }" : "=r"(a) : "l"(p));
    return a;
}
__device__ __forceinline__ void cp_async16(uint32_t dst, const void* src) {
    asm volatile("cp.async.cg.shared.global [%0], [%1], 16;" :: "r"(dst), "l"(src) : "memory");
}
#define CP_COMMIT() asm volatile("cp.async.commit_group;" ::: "memory")
#define CP_WAIT0()  asm volatile("cp.async.wait_group 0;" ::: "memory")

__device__ __forceinline__ void ldsm4(uint32_t* r, uint32_t addr) {
    asm volatile("ldmatrix.sync.aligned.m8n8.x4.shared.b16 {%0,%1,%2,%3}, [%4];"
        : "=r"(r[0]), "=r"(r[1]), "=r"(r[2]), "=r"(r[3]) : "r"(addr));
}
__device__ __forceinline__ void mma_f16(float* d, const uint32_t* a, const uint32_t* b) {
    asm volatile(
        "mma.sync.aligned.m16n8k16.row.col.f32.f16.f16.f32 "
        "{%0,%1,%2,%3}, {%4,%5,%6,%7}, {%8,%9}, {%0,%1,%2,%3};"
        : "+f"(d[0]), "+f"(d[1]), "+f"(d[2]), "+f"(d[3])
        : "r"(a[0]), "r"(a[1]), "r"(a[2]), "r"(a[3]), "r"(b[0]), "r"(b[1]));
}
__device__ __forceinline__ uint32_t packh2(float x, float y) {
    __half2 h = __floats2half2_rn(x, y);
    return *reinterpret_cast<uint32_t*>(&h);
}

// ================= Kernel 0: data prep =================
// y <  16 : transpose+convert W1[0:1024] -> g_W1h[j][d]   (64x64 tiles)
// y 16-17 : convert f -> g_fh
// y 18-21 : transpose+convert W2 -> g_W2h[l][k]
__global__ __launch_bounds__(256) void k0_prep(
    const float* __restrict__ f, const float* __restrict__ W1,
    const float* __restrict__ W2)
{
    const int t = threadIdx.x;
    if (blockIdx.y < 16) {
        __shared__ float tile[64][65];
        const int d0  = blockIdx.x * 64;
        const int jg0 = blockIdx.y * 64;
        const int rbase = (jg0 >= 512 ? 512 : 0) + d0;
        const int cbase = jg0 & 511;
        #pragma unroll
        for (int i = 0; i < 16; i++) {
            int idx = i * 256 + t;
            int r = idx >> 6, cc = idx & 63;
            tile[r][cc] = W1[(rbase + r) * D + cbase + cc];
        }
        __syncthreads();
        #pragma unroll
        for (int j = 0; j < 2; j++) {
            int row = j * 32 + (t >> 3);
            int ch  = t & 7;
            uint32_t hp[4];
            #pragma unroll
            for (int q = 0; q < 4; q++)
                hp[q] = packh2(tile[ch * 8 + 2 * q][row], tile[ch * 8 + 2 * q + 1][row]);
            *reinterpret_cast<uint4*>(&g_W1h[(jg0 + row) * D + d0 + ch * 8]) =
                make_uint4(hp[0], hp[1], hp[2], hp[3]);
        }
        return;
    }
    if (blockIdx.y < 18) {
        int gid = ((blockIdx.y - 16) * 8 + blockIdx.x) * 256 + t;
        #pragma unroll
        for (int i = 0; i < 32; i++) {
            int p4 = gid + i * 4096;
            float4 v = *reinterpret_cast<const float4*>(&f[p4 * 4]);
            uint2 o;
            o.x = packh2(v.x, v.y);
            o.y = packh2(v.z, v.w);
            *reinterpret_cast<uint2*>(&g_fh[p4 * 4]) = o;
        }
        return;
    }
    {
        __shared__ float tile[64][65];
        const int k0 = blockIdx.x * 64;
        const int l0 = (blockIdx.y - 18) * 64;
        #pragma unroll
        for (int i = 0; i < 16; i++) {
            int idx = i * 256 + t;
            int r = idx >> 6, cc = idx & 63;
            tile[r][cc] = W2[(k0 + r) * L2DIM + l0 + cc];
        }
        __syncthreads();
        #pragma unroll
        for (int j = 0; j < 2; j++) {
            int row = j * 32 + (t >> 3);
            int ch  = t & 7;
            uint32_t hp[4];
            #pragma unroll
            for (int q = 0; q < 4; q++)
                hp[q] = packh2(tile[ch * 8 + 2 * q][row], tile[ch * 8 + 2 * q + 1][row]);
            *reinterpret_cast<uint4*>(&g_W2h[(l0 + row) * D + k0 + ch * 8]) =
                make_uint4(hp[0], hp[1], hp[2], hp[3]);
        }
    }
}

// ================= Kernel 1: fp16 mma GEMM  C = f @ [W1a|W1b]^T =================
#define K1_FOFF 0
#define K1_WOFF 10240
#define K1_PC0  30720
#define K1_PC1  31232
#define K1_B1   31744
__global__ __launch_bounds__(256, 1) void k1_mma(
    const float* __restrict__ pos, const float* __restrict__ W1,
    const float* __restrict__ b1)
{
    __shared__ __align__(16) char sm[32256];
    const uint32_t sb = smem_u32(sm);
    float* pc0s = (float*)(sm + K1_PC0);
    float* pc1s = (float*)(sm + K1_PC1);
    float* b1s  = (float*)(sm + K1_B1);

    const int t = threadIdx.x, wid = t >> 5, lane = t & 31;
    const int wm = wid >> 2, wl = wid & 3;
    const int m0 = wm * 32, l0 = wl * 32;
    const int j0   = blockIdx.x * 128;
    const int row0 = blockIdx.y * 64;
    const int jc   = j0 & 511;
    const bool isA = (j0 < 512);

    if (t < 128) {
        pc0s[t] = W1[(2 * D) * D + jc + t];
        pc1s[t] = W1[(2 * D + 1) * D + jc + t];
        b1s[t]  = b1[jc + t];
    }

    const int frow = t >> 2, fch = t & 3;
    const int wrow = t >> 1, wch = (t & 1) * 2;

    float acc[2][4][4];
    #pragma unroll
    for (int mt = 0; mt < 2; mt++)
        #pragma unroll
        for (int nt = 0; nt < 4; nt++)
            #pragma unroll
            for (int c = 0; c < 4; c++) acc[mt][nt][c] = 0.f;

    cp_async16(sb + K1_FOFF + frow * HROWB + fch * 16, &g_fh[(row0 + frow) * D + fch * 8]);
    cp_async16(sb + K1_WOFF + wrow * WROWB + wch * 16,       &g_W1h[(j0 + wrow) * D + wch * 8]);
    cp_async16(sb + K1_WOFF + wrow * WROWB + (wch + 1) * 16, &g_W1h[(j0 + wrow) * D + (wch + 1) * 8]);
    CP_COMMIT();
    CP_WAIT0();
    __syncthreads();

    const int fr = lane & 15, fc = lane >> 4;

    for (int c = 0; c < CHUNKS; c++) {
        const int buf = c & 1;
        const bool more = (c + 1 < CHUNKS);

        if (more) {
            const int kn = (c + 1) * KC;
            cp_async16(sb + K1_FOFF + (buf ^ 1) * 64 * HROWB + frow * HROWB + fch * 16,
                       &g_fh[(row0 + frow) * D + kn + fch * 8]);
            cp_async16(sb + K1_WOFF + (buf ^ 1) * 128 * WROWB + wrow * WROWB + wch * 16,
                       &g_W1h[(j0 + wrow) * D + kn + wch * 8]);
            cp_async16(sb + K1_WOFF + (buf ^ 1) * 128 * WROWB + wrow * WROWB + (wch + 1) * 16,
                       &g_W1h[(j0 + wrow) * D + kn + (wch + 1) * 8]);
            CP_COMMIT();
        }

        const uint32_t Fb = sb + K1_FOFF + buf * 64 * HROWB;
        const uint32_t Wb = sb + K1_WOFF + buf * 128 * WROWB;
        #pragma unroll
        for (int ks = 0; ks < 2; ks++) {
            const int kb = ks * 32 + fc * 16;
            uint32_t af[2][4];
            #pragma unroll
            for (int mt = 0; mt < 2; mt++)
                ldsm4(af[mt], Fb + (m0 + mt * 16 + fr) * HROWB + kb);
            uint32_t bf[2][4];
            #pragma unroll
            for (int g = 0; g < 2; g++)
                ldsm4(bf[g], Wb + (l0 + g * 16 + fr) * WROWB + kb);
            #pragma unroll
            for (int mt = 0; mt < 2; mt++)
                #pragma unroll
                for (int g = 0; g < 2; g++) {
                    uint32_t blo[2] = {bf[g][0], bf[g][2]};
                    uint32_t bhi[2] = {bf[g][1], bf[g][3]};
                    mma_f16(acc[mt][2 * g],     af[mt], blo);
                    mma_f16(acc[mt][2 * g + 1], af[mt], bhi);
                }
        }
        CP_WAIT0();
        __syncthreads();
    }

    const int lr = lane >> 2, lc = lane & 3;
    #pragma unroll
    for (int mt = 0; mt < 2; mt++) {
        #pragma unroll
        for (int half = 0; half < 2; half++) {
            int row = row0 + m0 + mt * 16 + lr + half * 8;
            float p0 = pos[row * 2 + 0];
            float p1 = pos[row * 2 + 1];
            #pragma unroll
            for (int nt = 0; nt < 4; nt++) {
                int jl = l0 + nt * 8 + 2 * lc;
                float c0 = acc[mt][nt][half * 2 + 0];
                float c1 = acc[mt][nt][half * 2 + 1];
                float pcv0 = p0 * pc0s[jl]     + p1 * pc1s[jl];
                float pcv1 = p0 * pc0s[jl + 1] + p1 * pc1s[jl + 1];
                float2 o;
                if (isA) {
                    o.x = c0 + pcv0 + b1s[jl];
                    o.y = c1 + pcv1 + b1s[jl + 1];
                    *reinterpret_cast<float2*>(&g_A[row * D + jc + jl]) = o;
                } else {
                    o.x = c0 - pcv0;
                    o.y = c1 - pcv1;
                    *reinterpret_cast<float2*>(&g_B[row * D + jc + jl]) = o;
                }
            }
        }
    }
}

// ================= Kernel 2: fp16 mma.sync GEMM per (b,n) — proven 147us config
// with hoisted LDSM base addresses + earlier Bt prefetch.
__global__ __launch_bounds__(512, 1) void k2_mma(
    const float* __restrict__ b2, const float* __restrict__ W3,
    const float* __restrict__ b3, float* __restrict__ out)
{
    extern __shared__ char smem[];
    const uint32_t sb = smem_u32(smem);
    float* aR   = (float*)(smem + OFF_AROW);
    float* b2s  = (float*)(smem + OFF_B2);
    float* w3s  = (float*)(smem + OFF_W3);
    float* part = (float*)(smem + OFF_PART);

    const int t = threadIdx.x, wid = t >> 5, lane = t & 31;
    const int wm = wid >> 2, wl = wid & 3;
    const int m0 = wm * 32, l0 = wl * 64;
    const int bn = blockIdx.x, b = bn >> 7;
    const float* Btb = g_B + (size_t)b * NPAIR * D;

    // staging roles
    const int hrow = t >> 2;            // H row (4 thr/row, 128 rows)
    const int hch  = t & 3;             // 16B chunk (8 fp16 = 8 k)
    const int wrow = t >> 1;            // W row (2 thr/row, 256 rows)
    const int wch  = (t & 1) * 2;       // chunk base (2 chunks of 16B each thread)

    if (t < 256) { b2s[t] = b2[t]; aR[t] = g_A[bn * D + t]; }
    else { int u = t - 256; aR[u + 256] = g_A[bn * D + 256 + u]; }
    #pragma unroll
    for (int i = 0; i < 2; i++) w3s[t + i * 512] = W3[t + i * 512];
    __syncthreads();

    float acc[2][8][4];
    #pragma unroll
    for (int mt = 0; mt < 2; mt++)
        #pragma unroll
        for (int nt = 0; nt < 8; nt++)
            #pragma unroll
            for (int c = 0; c < 4; c++) acc[mt][nt][c] = 0.f;

    // ---- chunk 0: cp.async W, LDG+STS H ----
    {
        uint32_t wdst = sb + OFF_W + wrow * WROWB + wch * 16;
        cp_async16(wdst,      &g_W2h[wrow * D + wch * 8]);
        cp_async16(wdst + 16, &g_W2h[wrow * D + wch * 8 + 8]);
        CP_COMMIT();

        float4 v0 = *reinterpret_cast<const float4*>(&Btb[hrow * D + hch * 8]);
        float4 v1 = *reinterpret_cast<const float4*>(&Btb[hrow * D + hch * 8 + 4]);
        const float* ar = aR + hch * 8;
        uint32_t hp[4];
        hp[0] = packh2(fmaxf(v0.x + ar[0], 0.f), fmaxf(v0.y + ar[1], 0.f));
        hp[1] = packh2(fmaxf(v0.z + ar[2], 0.f), fmaxf(v0.w + ar[3], 0.f));
        hp[2] = packh2(fmaxf(v1.x + ar[4], 0.f), fmaxf(v1.y + ar[5], 0.f));
        hp[3] = packh2(fmaxf(v1.z + ar[6], 0.f), fmaxf(v1.w + ar[7], 0.f));
        *reinterpret_cast<uint4*>((char*)smem + OFF_H + hrow * HROWB + hch * 16) =
            make_uint4(hp[0], hp[1], hp[2], hp[3]);
        CP_WAIT0();
        __syncthreads();
    }

    const int fr = lane & 15;            // ldmatrix row within 16
    const int fc = lane >> 4;            // ldmatrix 16B-chunk (0/1)

    // hoisted LDSM base addresses (buf 0); buf toggles by constant strides
    const uint32_t hBase = sb + OFF_H + (m0 + fr) * HROWB + fc * 16;
    const uint32_t wBase = sb + OFF_W + (l0 + fr) * WROWB + fc * 16;

    for (int c = 0; c < CHUNKS; c++) {
        const int buf = c & 1;
        const bool more = (c + 1 < CHUNKS);
        float4 rB0, rB1;

        if (more) {
            const int kn = (c + 1) * KC;
            // Bt LDGs first: longest-latency loads drain earliest
            rB0 = *reinterpret_cast<const float4*>(&Btb[hrow * D + kn + hch * 8]);
            rB1 = *reinterpret_cast<const float4*>(&Btb[hrow * D + kn + hch * 8 + 4]);
            uint32_t wdst = sb + OFF_W + (buf ^ 1) * 256 * WROWB + wrow * WROWB + wch * 16;
            cp_async16(wdst,      &g_W2h[wrow * D + kn + wch * 8]);
            cp_async16(wdst + 16, &g_W2h[wrow * D + kn + wch * 8 + 8]);
            CP_COMMIT();
        }

        // ---- compute chunk c: 2 k-steps of 16 ----
        const uint32_t Hb = hBase + buf * (128 * HROWB);
        const uint32_t Wb = wBase + buf * (256 * WROWB);
        #pragma unroll
        for (int ks = 0; ks < 2; ks++) {
            const int kb = ks * 32;
            uint32_t af[2][4];
            #pragma unroll
            for (int mt = 0; mt < 2; mt++)
                ldsm4(af[mt], Hb + mt * (16 * HROWB) + kb);
            uint32_t bf[4][4];
            #pragma unroll
            for (int g = 0; g < 4; g++)
                ldsm4(bf[g], Wb + g * (16 * WROWB) + kb);
            #pragma unroll
            for (int mt = 0; mt < 2; mt++)
                #pragma unroll
                for (int g = 0; g < 4; g++) {
                    uint32_t blo[2] = {bf[g][0], bf[g][2]};
                    uint32_t bhi[2] = {bf[g][1], bf[g][3]};
                    mma_f16(acc[mt][2 * g],     af[mt], blo);
                    mma_f16(acc[mt][2 * g + 1], af[mt], bhi);
                }
        }

        if (more) {
            const float* ar = aR + (c + 1) * KC + hch * 8;
            uint32_t hp[4];
            hp[0] = packh2(fmaxf(rB0.x + ar[0], 0.f), fmaxf(rB0.y + ar[1], 0.f));
            hp[1] = packh2(fmaxf(rB0.z + ar[2], 0.f), fmaxf(rB0.w + ar[3], 0.f));
            hp[2] = packh2(fmaxf(rB1.x + ar[4], 0.f), fmaxf(rB1.y + ar[5], 0.f));
            hp[3] = packh2(fmaxf(rB1.z + ar[6], 0.f), fmaxf(rB1.w + ar[7], 0.f));
            *reinterpret_cast<uint4*>((char*)smem + OFF_H + (buf ^ 1) * 128 * HROWB + hrow * HROWB + hch * 16) =
                make_uint4(hp[0], hp[1], hp[2], hp[3]);
        }
        CP_WAIT0();
        __syncthreads();
    }

    // ---- epilogue: relu(acc + b2) @ W3, reduce over l-warps ----
    const int lr = lane >> 2, lc = lane & 3;
    #pragma unroll
    for (int mt = 0; mt < 2; mt++) {
        float o0[4] = {0.f, 0.f, 0.f, 0.f};
        float o1[4] = {0.f, 0.f, 0.f, 0.f};
        #pragma unroll
        for (int nt = 0; nt < 8; nt++) {
            int lcol = l0 + 8 * nt + 2 * lc;
            float vb0 = b2s[lcol], vb1 = b2s[lcol + 1];
            const float* w30 = &w3s[lcol * 4];
            const float* w31 = &w3s[(lcol + 1) * 4];
            float v00 = fmaxf(acc[mt][nt][0] + vb0, 0.f);
            float v01 = fmaxf(acc[mt][nt][1] + vb1, 0.f);
            float v10 = fmaxf(acc[mt][nt][2] + vb0, 0.f);
            float v11 = fmaxf(acc[mt][nt][3] + vb1, 0.f);
            #pragma unroll
            for (int o = 0; o < 4; o++) {
                o0[o] += v00 * w30[o] + v01 * w31[o];
                o1[o] += v10 * w30[o] + v11 * w31[o];
            }
        }
        #pragma unroll
        for (int off = 1; off <= 2; off <<= 1) {
            #pragma unroll
            for (int o = 0; o < 4; o++) {
                o0[o] += __shfl_xor_sync(0xffffffffu, o0[o], off);
                o1[o] += __shfl_xor_sync(0xffffffffu, o1[o], off);
            }
        }
        if (lc == 0) {
            int r0 = m0 + 16 * mt + lr;
            #pragma unroll
            for (int o = 0; o < 4; o++) {
                part[r0 * 16 + wl * 4 + o] = o0[o];
                part[(r0 + 8) * 16 + wl * 4 + o] = o1[o];
            }
        }
    }
    __syncthreads();

    if (t < 128) {
        float4 r;
        float s[4];
        #pragma unroll
        for (int o = 0; o < 4; o++) {
            s[o] = b3[o];
            #pragma unroll
            for (int w = 0; w < 4; w++) s[o] += part[t * 16 + w * 4 + o];
        }
        r.x = s[0]; r.y = s[1]; r.z = s[2]; r.w = s[3];
        *reinterpret_cast<float4*>(&out[((size_t)bn * NPAIR + t) * 4]) = r;
    }
}

extern "C" void kernel_launch(void* const* d_in, const int* in_sizes, int n_in,
                              void* d_out, int out_size)
{
    const float* f   = (const float*)d_in[0];
    const float* pos = (const float*)d_in[1];
    const float* W1  = (const float*)d_in[2];
    const float* b1  = (const float*)d_in[3];
    const float* W2  = (const float*)d_in[4];
    const float* b2  = (const float*)d_in[5];
    const float* W3  = (const float*)d_in[6];
    const float* b3  = (const float*)d_in[7];
    float* out = (float*)d_out;

    cudaFuncSetAttribute(k2_mma, cudaFuncAttributeMaxDynamicSharedMemorySize, SMEM_TOTAL);

    k0_prep<<<dim3(8, 22), 256>>>(f, W1, W2);
    k1_mma<<<dim3(8, 16), 256>>>(pos, W1, b1);
    k2_mma<<<1024, 512, SMEM_TOTAL>>>(b2, W3, b3, out);
}